// round 2
// baseline (speedup 1.0000x reference)
#include <cuda_runtime.h>
#include <cuda_bf16.h>
#include <cstdint>

// Problem constants
constexpr int T_DIM = 256;
constexpr int B_DIM = 256;
constexpr int IN_DIM = 1024;
constexpr int H_DIM = 1024;
constexpr int M1 = T_DIM * B_DIM;   // 65536 rows for phase-1 GEMM

// Split-K partial buffers for the recurrence GEMM (2 slabs of [B, H])
__device__ float g_part[2][B_DIM * H_DIM];
// Per-tile completion counters (128 tiles of 64x32). Kernel leaves them at 0.
__device__ int g_cnt[128];

// ---------------------------------------------------------------------------
// Packed f32x2 helpers (Blackwell FFMA2 — double-rate fp32)
// ---------------------------------------------------------------------------
__device__ __forceinline__ unsigned long long pack2(float lo, float hi) {
    unsigned long long r;
    asm("mov.b64 %0, {%1, %2};" : "=l"(r) : "f"(lo), "f"(hi));
    return r;
}
__device__ __forceinline__ unsigned long long ffma2(unsigned long long a,
                                                    unsigned long long b,
                                                    unsigned long long c) {
    unsigned long long d;
    asm("fma.rn.f32x2 %0, %1, %2, %3;" : "=l"(d) : "l"(a), "l"(b), "l"(c));
    return d;
}
__device__ __forceinline__ float2 unpack2(unsigned long long v) {
    float2 f;
    asm("mov.b64 {%0, %1}, %2;" : "=f"(f.x), "=f"(f.y) : "l"(v));
    return f;
}

// ---------------------------------------------------------------------------
// Phase 1: xi[m, n] = sum_k x[m,k] * Wi[n,k] + bi[n]
// M=65536, N=1024, K=1024.  BM=BN=128, BK=8, 256 threads, 8x8 per thread.
// Writes directly into d_out (xi occupies the same [T,B,H] layout).
// ---------------------------------------------------------------------------
__global__ __launch_bounds__(256) void gemm_xi_kernel(
    const float* __restrict__ A,     // x  [M1, IN]
    const float* __restrict__ Bw,    // Wi [H, IN]
    const float* __restrict__ bias,  // bi [H]
    float* __restrict__ C)           // xi -> d_out [M1, H]
{
    __shared__ float As[8][128];
    __shared__ float Bs[8][128];

    const int tid = threadIdx.x;
    const int m0 = blockIdx.y * 128;
    const int n0 = blockIdx.x * 128;
    const int tx = tid & 15;   // column group: 8 cols each
    const int ty = tid >> 4;   // row group:    8 rows each
    const int lr = tid >> 1;   // load row within tile (0..127)
    const int lc = (tid & 1) * 4;  // load col offset (0 or 4)

    unsigned long long acc[8][4];
#pragma unroll
    for (int i = 0; i < 8; i++)
#pragma unroll
        for (int j = 0; j < 4; j++) acc[i][j] = 0ull;

    const float* aLoad = A + (size_t)(m0 + lr) * IN_DIM + lc;
    const float* bLoad = Bw + (size_t)(n0 + lr) * IN_DIM + lc;

    for (int k0 = 0; k0 < IN_DIM; k0 += 8) {
        float4 av = *reinterpret_cast<const float4*>(aLoad + k0);
        float4 bv = *reinterpret_cast<const float4*>(bLoad + k0);
        As[lc + 0][lr] = av.x; As[lc + 1][lr] = av.y;
        As[lc + 2][lr] = av.z; As[lc + 3][lr] = av.w;
        Bs[lc + 0][lr] = bv.x; Bs[lc + 1][lr] = bv.y;
        Bs[lc + 2][lr] = bv.z; Bs[lc + 3][lr] = bv.w;
        __syncthreads();

#pragma unroll
        for (int k = 0; k < 8; k++) {
            float4 a0 = *reinterpret_cast<const float4*>(&As[k][ty * 8]);
            float4 a1 = *reinterpret_cast<const float4*>(&As[k][ty * 8 + 4]);
            ulonglong2 b01 = *reinterpret_cast<const ulonglong2*>(&Bs[k][tx * 8]);
            ulonglong2 b23 = *reinterpret_cast<const ulonglong2*>(&Bs[k][tx * 8 + 4]);
            float a[8] = {a0.x, a0.y, a0.z, a0.w, a1.x, a1.y, a1.z, a1.w};
#pragma unroll
            for (int i = 0; i < 8; i++) {
                unsigned long long a2 = pack2(a[i], a[i]);
                acc[i][0] = ffma2(a2, b01.x, acc[i][0]);
                acc[i][1] = ffma2(a2, b01.y, acc[i][1]);
                acc[i][2] = ffma2(a2, b23.x, acc[i][2]);
                acc[i][3] = ffma2(a2, b23.y, acc[i][3]);
            }
        }
        __syncthreads();
    }

    // Epilogue: add bias, store
    float bb[8];
#pragma unroll
    for (int j = 0; j < 8; j++) bb[j] = bias[n0 + tx * 8 + j];

#pragma unroll
    for (int i = 0; i < 8; i++) {
        float c[8];
#pragma unroll
        for (int j = 0; j < 4; j++) {
            float2 v = unpack2(acc[i][j]);
            c[2 * j + 0] = v.x + bb[2 * j + 0];
            c[2 * j + 1] = v.y + bb[2 * j + 1];
        }
        float* cp = C + (size_t)(m0 + ty * 8 + i) * H_DIM + n0 + tx * 8;
        *reinterpret_cast<float4*>(cp + 0) = make_float4(c[0], c[1], c[2], c[3]);
        *reinterpret_cast<float4*>(cp + 4) = make_float4(c[4], c[5], c[6], c[7]);
    }
}

// ---------------------------------------------------------------------------
// Phase 2: fused per-step recurrence GEMM + epilogue, split-K=2.
// Tile: 64(M) x 32(N), BK=16, K half = 512 (32 stages), double-buffered smem.
// A tile stored PRE-DUPLICATED as (a,a) float2 pairs -> pack-free FFMA2.
// The second CTA to finish a tile performs the reduction + tanh epilogue.
// Grid (32, 4, 2) = 256 CTAs, 256 threads.
// ---------------------------------------------------------------------------
__global__ __launch_bounds__(256) void gemm_h_fused(
    const float* __restrict__ Hprev,  // [B, H]
    const float* __restrict__ W,      // Wh [H, H]
    const float* __restrict__ xi,     // xi_t (= d_out + t*B*H)
    const float* __restrict__ bh,     // Wh_b [H]
    float* __restrict__ hout)         // h_t (same buffer as xi)
{
    __shared__ float2 As2[2][16][64];  // [buf][k][row] duplicated (a,a): 16KB
    __shared__ float  Bs[2][16][32];   // [buf][k][col]: 4KB
    __shared__ int s_last;

    const int tid = threadIdx.x;
    const int m0 = blockIdx.y * 64;
    const int n0 = blockIdx.x * 32;
    const int kz = blockIdx.z;
    const int tile = blockIdx.y * 32 + blockIdx.x;   // 0..127

    // Compute mapping: 8 outputs/thread = 2 rows x 4 cols
    const int ty = tid >> 3;          // 0..31 -> row pair base 2*ty
    const int tx = tid & 7;           // 0..7  -> cols 4*tx..4*tx+3

    // Loader mapping
    const int a_row = tid >> 2;              // 0..63
    const int a_kq  = (tid & 3) << 2;        // 0,4,8,12
    const int b_col = tid >> 2;              // 0..31 (only tid<128 valid)
    const bool b_on = (tid < 128);

    const float* aG = Hprev + (size_t)(m0 + a_row) * H_DIM + kz * 512 + a_kq;
    const float* bG = W + (size_t)(n0 + b_col) * H_DIM + kz * 512 + a_kq;

    ulonglong2 acc0 = make_ulonglong2(0ull, 0ull);   // row 2ty
    ulonglong2 acc1 = make_ulonglong2(0ull, 0ull);   // row 2ty+1

    float4 av, bv;

    // Prologue: stage 0
    av = *reinterpret_cast<const float4*>(aG);
    if (b_on) bv = *reinterpret_cast<const float4*>(bG);
    {
        As2[0][a_kq + 0][a_row] = make_float2(av.x, av.x);
        As2[0][a_kq + 1][a_row] = make_float2(av.y, av.y);
        As2[0][a_kq + 2][a_row] = make_float2(av.z, av.z);
        As2[0][a_kq + 3][a_row] = make_float2(av.w, av.w);
        if (b_on) {
            Bs[0][a_kq + 0][b_col] = bv.x;
            Bs[0][a_kq + 1][b_col] = bv.y;
            Bs[0][a_kq + 2][b_col] = bv.z;
            Bs[0][a_kq + 3][b_col] = bv.w;
        }
    }
    __syncthreads();

#pragma unroll 2
    for (int s = 0; s < 32; s++) {
        const int buf = s & 1;
        // Prefetch next stage (global -> regs)
        if (s + 1 < 32) {
            av = *reinterpret_cast<const float4*>(aG + (s + 1) * 16);
            if (b_on) bv = *reinterpret_cast<const float4*>(bG + (s + 1) * 16);
        }

        // Compute current stage
        const float2* aP = &As2[buf][0][2 * ty];
        const float*  bP = &Bs[buf][0][4 * tx];
#pragma unroll
        for (int k = 0; k < 16; k++) {
            ulonglong2 aa = *reinterpret_cast<const ulonglong2*>(aP + k * 64);
            ulonglong2 bb = *reinterpret_cast<const ulonglong2*>(bP + k * 32);
            acc0.x = ffma2(aa.x, bb.x, acc0.x);
            acc0.y = ffma2(aa.x, bb.y, acc0.y);
            acc1.x = ffma2(aa.y, bb.x, acc1.x);
            acc1.y = ffma2(aa.y, bb.y, acc1.y);
        }

        // Store next stage into the other buffer
        if (s + 1 < 32) {
            const int nb = buf ^ 1;
            As2[nb][a_kq + 0][a_row] = make_float2(av.x, av.x);
            As2[nb][a_kq + 1][a_row] = make_float2(av.y, av.y);
            As2[nb][a_kq + 2][a_row] = make_float2(av.z, av.z);
            As2[nb][a_kq + 3][a_row] = make_float2(av.w, av.w);
            if (b_on) {
                Bs[nb][a_kq + 0][b_col] = bv.x;
                Bs[nb][a_kq + 1][b_col] = bv.y;
                Bs[nb][a_kq + 2][b_col] = bv.z;
                Bs[nb][a_kq + 3][b_col] = bv.w;
            }
        }
        __syncthreads();
    }

    // Unpack accumulators
    const int r0 = m0 + 2 * ty;
    const int r1 = r0 + 1;
    const int c = n0 + 4 * tx;

    float2 u00 = unpack2(acc0.x), u01 = unpack2(acc0.y);
    float2 u10 = unpack2(acc1.x), u11 = unpack2(acc1.y);
    float4 P0 = make_float4(u00.x, u00.y, u01.x, u01.y);
    float4 P1 = make_float4(u10.x, u10.y, u11.x, u11.y);

    // Publish partial
    *reinterpret_cast<float4*>(&g_part[kz][(size_t)r0 * H_DIM + c]) = P0;
    *reinterpret_cast<float4*>(&g_part[kz][(size_t)r1 * H_DIM + c]) = P1;
    __threadfence();
    __syncthreads();
    if (tid == 0) {
        int old = atomicAdd(&g_cnt[tile], 1);
        s_last = (old == 1);
    }
    __syncthreads();
    if (!s_last) return;

    // Last CTA for this tile: reduce + epilogue
    const float* part = g_part[1 - kz];
    float4 q0 = __ldcg(reinterpret_cast<const float4*>(&part[(size_t)r0 * H_DIM + c]));
    float4 q1 = __ldcg(reinterpret_cast<const float4*>(&part[(size_t)r1 * H_DIM + c]));
    float4 x0 = *reinterpret_cast<const float4*>(&xi[(size_t)r0 * H_DIM + c]);
    float4 x1 = *reinterpret_cast<const float4*>(&xi[(size_t)r1 * H_DIM + c]);
    float4 bb4 = *reinterpret_cast<const float4*>(&bh[c]);

    float4 o0, o1;
    o0.x = tanhf(P0.x + q0.x + x0.x + bb4.x);
    o0.y = tanhf(P0.y + q0.y + x0.y + bb4.y);
    o0.z = tanhf(P0.z + q0.z + x0.z + bb4.z);
    o0.w = tanhf(P0.w + q0.w + x0.w + bb4.w);
    o1.x = tanhf(P1.x + q1.x + x1.x + bb4.x);
    o1.y = tanhf(P1.y + q1.y + x1.y + bb4.y);
    o1.z = tanhf(P1.z + q1.z + x1.z + bb4.z);
    o1.w = tanhf(P1.w + q1.w + x1.w + bb4.w);

    *reinterpret_cast<float4*>(&hout[(size_t)r0 * H_DIM + c]) = o0;
    *reinterpret_cast<float4*>(&hout[(size_t)r1 * H_DIM + c]) = o1;

    // Reset counter for the next step's launch
    if (tid == 0) g_cnt[tile] = 0;
}

// ---------------------------------------------------------------------------
// Launch
// inputs: 0=x [T,B,IN], 1=h [B,H], 2=Wi_w [H,IN], 3=Wi_b [H],
//         4=Wh_w [H,H], 5=Wh_b [H];  output: hiddens [T,B,H]
// ---------------------------------------------------------------------------
extern "C" void kernel_launch(void* const* d_in, const int* in_sizes, int n_in,
                              void* d_out, int out_size) {
    const float* x   = (const float*)d_in[0];
    const float* h0  = (const float*)d_in[1];
    const float* Wi  = (const float*)d_in[2];
    const float* bi  = (const float*)d_in[3];
    const float* Wh  = (const float*)d_in[4];
    const float* bh  = (const float*)d_in[5];
    float* out = (float*)d_out;

    // Phase 1: xi for all timesteps, written straight into d_out
    gemm_xi_kernel<<<dim3(H_DIM / 128, M1 / 128), 256>>>(x, Wi, bi, out);

    // Phase 2: sequential recurrence, fused GEMM+epilogue, in place on d_out
    for (int t = 0; t < T_DIM; t++) {
        const float* hprev = (t == 0) ? h0 : out + (size_t)(t - 1) * B_DIM * H_DIM;
        float* xt = out + (size_t)t * B_DIM * H_DIM;
        gemm_h_fused<<<dim3(32, 4, 2), 256>>>(hprev, Wh, xt, bh, xt);
    }
}

// round 3
// speedup vs baseline: 1.4046x; 1.4046x over previous
#include <cuda_runtime.h>
#include <cuda_bf16.h>
#include <cstdint>

// Problem constants
constexpr int T_DIM = 256;
constexpr int B_DIM = 256;
constexpr int IN_DIM = 1024;
constexpr int H_DIM = 1024;
constexpr int M1 = T_DIM * B_DIM;     // 65536 rows for phase-1 GEMM
constexpr int BH = B_DIM * H_DIM;     // one [B,H] slab

// Persistent-kernel step barrier: one counter per timestep.
__device__ int g_cnt[T_DIM];

constexpr int N_CTAS = 128;           // 4 M-tiles x 32 N-tiles
constexpr int SMEM_BYTES = H_DIM * 32 * 4;   // Wh slice [1024][32] = 128KB

// ---------------------------------------------------------------------------
// Packed f32x2 helpers (Blackwell FFMA2 — double-rate fp32)
// ---------------------------------------------------------------------------
__device__ __forceinline__ unsigned long long pack2(float lo, float hi) {
    unsigned long long r;
    asm("mov.b64 %0, {%1, %2};" : "=l"(r) : "f"(lo), "f"(hi));
    return r;
}
__device__ __forceinline__ unsigned long long ffma2(unsigned long long a,
                                                    unsigned long long b,
                                                    unsigned long long c) {
    unsigned long long d;
    asm("fma.rn.f32x2 %0, %1, %2, %3;" : "=l"(d) : "l"(a), "l"(b), "l"(c));
    return d;
}
__device__ __forceinline__ float2 unpack2(unsigned long long v) {
    float2 f;
    asm("mov.b64 {%0, %1}, %2;" : "=f"(f.x), "=f"(f.y) : "l"(v));
    return f;
}

// ---------------------------------------------------------------------------
// Reset kernel: zero the step counters (runs once per replay, before phase 2)
// ---------------------------------------------------------------------------
__global__ void reset_kernel() {
    if (threadIdx.x < T_DIM) g_cnt[threadIdx.x] = 0;
}

// ---------------------------------------------------------------------------
// Phase 1: xi[m, n] = sum_k x[m,k] * Wi[n,k] + bi[n]
// M=65536, N=1024, K=1024.  BM=BN=128, BK=8, 256 threads, 8x8 per thread.
// Writes directly into d_out (xi occupies the same [T,B,H] layout).
// ---------------------------------------------------------------------------
__global__ __launch_bounds__(256) void gemm_xi_kernel(
    const float* __restrict__ A,     // x  [M1, IN]
    const float* __restrict__ Bw,    // Wi [H, IN]
    const float* __restrict__ bias,  // bi [H]
    float* __restrict__ C)           // xi -> d_out [M1, H]
{
    __shared__ float As[8][128];
    __shared__ float Bs[8][128];

    const int tid = threadIdx.x;
    const int m0 = blockIdx.y * 128;
    const int n0 = blockIdx.x * 128;
    const int tx = tid & 15;   // column group: 8 cols each
    const int ty = tid >> 4;   // row group:    8 rows each
    const int lr = tid >> 1;   // load row within tile (0..127)
    const int lc = (tid & 1) * 4;  // load col offset (0 or 4)

    unsigned long long acc[8][4];
#pragma unroll
    for (int i = 0; i < 8; i++)
#pragma unroll
        for (int j = 0; j < 4; j++) acc[i][j] = 0ull;

    const float* aLoad = A + (size_t)(m0 + lr) * IN_DIM + lc;
    const float* bLoad = Bw + (size_t)(n0 + lr) * IN_DIM + lc;

    for (int k0 = 0; k0 < IN_DIM; k0 += 8) {
        float4 av = *reinterpret_cast<const float4*>(aLoad + k0);
        float4 bv = *reinterpret_cast<const float4*>(bLoad + k0);
        As[lc + 0][lr] = av.x; As[lc + 1][lr] = av.y;
        As[lc + 2][lr] = av.z; As[lc + 3][lr] = av.w;
        Bs[lc + 0][lr] = bv.x; Bs[lc + 1][lr] = bv.y;
        Bs[lc + 2][lr] = bv.z; Bs[lc + 3][lr] = bv.w;
        __syncthreads();

#pragma unroll
        for (int k = 0; k < 8; k++) {
            float4 a0 = *reinterpret_cast<const float4*>(&As[k][ty * 8]);
            float4 a1 = *reinterpret_cast<const float4*>(&As[k][ty * 8 + 4]);
            ulonglong2 b01 = *reinterpret_cast<const ulonglong2*>(&Bs[k][tx * 8]);
            ulonglong2 b23 = *reinterpret_cast<const ulonglong2*>(&Bs[k][tx * 8 + 4]);
            float a[8] = {a0.x, a0.y, a0.z, a0.w, a1.x, a1.y, a1.z, a1.w};
#pragma unroll
            for (int i = 0; i < 8; i++) {
                unsigned long long a2 = pack2(a[i], a[i]);
                acc[i][0] = ffma2(a2, b01.x, acc[i][0]);
                acc[i][1] = ffma2(a2, b01.y, acc[i][1]);
                acc[i][2] = ffma2(a2, b23.x, acc[i][2]);
                acc[i][3] = ffma2(a2, b23.y, acc[i][3]);
            }
        }
        __syncthreads();
    }

    // Epilogue: add bias, store
    float bb[8];
#pragma unroll
    for (int j = 0; j < 8; j++) bb[j] = bias[n0 + tx * 8 + j];

#pragma unroll
    for (int i = 0; i < 8; i++) {
        float c[8];
#pragma unroll
        for (int j = 0; j < 4; j++) {
            float2 v = unpack2(acc[i][j]);
            c[2 * j + 0] = v.x + bb[2 * j + 0];
            c[2 * j + 1] = v.y + bb[2 * j + 1];
        }
        float* cp = C + (size_t)(m0 + ty * 8 + i) * H_DIM + n0 + tx * 8;
        *reinterpret_cast<float4*>(cp + 0) = make_float4(c[0], c[1], c[2], c[3]);
        *reinterpret_cast<float4*>(cp + 4) = make_float4(c[4], c[5], c[6], c[7]);
    }
}

// ---------------------------------------------------------------------------
// Phase 2: persistent recurrence kernel.
// Grid: 128 CTAs (4 M-tiles of 64 rows x 32 N-tiles of 32 cols), 256 threads.
// Each CTA keeps its Wh slice [1024 k][32 n] resident in 128KB smem for all
// 256 steps. Per step:
//   - A (h_prev rows) streamed from L2 via __ldcg (float4, double-buffered)
//   - B from smem (one LDS.128 per k, conflict-free broadcast)
//   - 4 FFMA2 per k per thread (2 rows x 4 cols outputs)
//   - fused epilogue: h = tanh(acc + xi + bh), written in place over xi
//   - device-wide step barrier on g_cnt[t]
// ---------------------------------------------------------------------------
__global__ __launch_bounds__(256, 1) void rnn_persistent(
    const float* __restrict__ h0,
    const float* __restrict__ Wh,
    const float* __restrict__ bh,
    float* __restrict__ out)
{
    extern __shared__ float Bs[];  // [1024][32] : Bs[k*32 + n]

    const int tid = threadIdx.x;
    const int n0 = blockIdx.x * 32;  // 0..31 tiles
    const int m0 = blockIdx.y * 64;  // 0..3 tiles

    // Load Wh slice (rows n0..n0+31, all K) into smem, transposed to [k][n].
    // One-time cost (~8 microseconds), amortized over 256 steps.
    for (int i = tid; i < 32 * (H_DIM / 4); i += 256) {
        const int n = i >> 8;                // 0..31
        const int kq = (i & 255) << 2;       // 0,4,...,1020
        float4 w = *reinterpret_cast<const float4*>(Wh + (size_t)(n0 + n) * H_DIM + kq);
        Bs[(kq + 0) * 32 + n] = w.x;
        Bs[(kq + 1) * 32 + n] = w.y;
        Bs[(kq + 2) * 32 + n] = w.z;
        Bs[(kq + 3) * 32 + n] = w.w;
    }

    const int tx = tid & 7;    // 0..7 -> cols c..c+3
    const int ty = tid >> 3;   // 0..31 -> rows r0, r0+1
    const int c = n0 + 4 * tx;
    const int r0 = m0 + 2 * ty;

    const float4 bb = *reinterpret_cast<const float4*>(bh + c);
    __syncthreads();

    for (int t = 0; t < T_DIM; t++) {
        const float* hp = (t == 0) ? h0 : (out + (size_t)(t - 1) * BH);
        const float* a0p = hp + (size_t)r0 * H_DIM;
        const float* a1p = a0p + H_DIM;

        unsigned long long acc00 = 0ull, acc01 = 0ull;
        unsigned long long acc10 = 0ull, acc11 = 0ull;

        // Double-buffered A registers, 4 k's per chunk
        float4 a0 = __ldcg(reinterpret_cast<const float4*>(a0p));
        float4 a1 = __ldcg(reinterpret_cast<const float4*>(a1p));

        for (int kb = 0; kb < H_DIM; kb += 4) {
            float4 na0, na1;
            if (kb + 4 < H_DIM) {
                na0 = __ldcg(reinterpret_cast<const float4*>(a0p + kb + 4));
                na1 = __ldcg(reinterpret_cast<const float4*>(a1p + kb + 4));
            }
            const float a0v[4] = {a0.x, a0.y, a0.z, a0.w};
            const float a1v[4] = {a1.x, a1.y, a1.z, a1.w};
#pragma unroll
            for (int j = 0; j < 4; j++) {
                ulonglong2 b2 = *reinterpret_cast<const ulonglong2*>(
                    &Bs[(kb + j) * 32 + 4 * tx]);
                unsigned long long pa0 = pack2(a0v[j], a0v[j]);
                unsigned long long pa1 = pack2(a1v[j], a1v[j]);
                acc00 = ffma2(pa0, b2.x, acc00);
                acc01 = ffma2(pa0, b2.y, acc01);
                acc10 = ffma2(pa1, b2.x, acc10);
                acc11 = ffma2(pa1, b2.y, acc11);
            }
            a0 = na0;
            a1 = na1;
        }

        // Fused epilogue: h = tanh(acc + xi + bh), in place over xi
        float* xo = out + (size_t)t * BH;
        float* p0 = xo + (size_t)r0 * H_DIM + c;
        float* p1 = p0 + H_DIM;
        float4 x0 = __ldcg(reinterpret_cast<const float4*>(p0));
        float4 x1 = __ldcg(reinterpret_cast<const float4*>(p1));

        float2 u00 = unpack2(acc00), u01 = unpack2(acc01);
        float2 u10 = unpack2(acc10), u11 = unpack2(acc11);

        float4 o0, o1;
        o0.x = tanhf(u00.x + x0.x + bb.x);
        o0.y = tanhf(u00.y + x0.y + bb.y);
        o0.z = tanhf(u01.x + x0.z + bb.z);
        o0.w = tanhf(u01.y + x0.w + bb.w);
        o1.x = tanhf(u10.x + x1.x + bb.x);
        o1.y = tanhf(u10.y + x1.y + bb.y);
        o1.z = tanhf(u11.x + x1.z + bb.z);
        o1.w = tanhf(u11.y + x1.w + bb.w);

        *reinterpret_cast<float4*>(p0) = o0;
        *reinterpret_cast<float4*>(p1) = o1;

        // Device-wide step barrier
        __syncthreads();          // all CTA stores done
        __threadfence();          // make them visible device-wide
        if (tid == 0) {
            atomicAdd(&g_cnt[t], 1);
            volatile int* p = &g_cnt[t];
            while (*p < N_CTAS) { }
        }
        __syncthreads();
        __threadfence();          // acquire: observe other CTAs' h writes
    }
}

// ---------------------------------------------------------------------------
// Launch
// inputs: 0=x [T,B,IN], 1=h [B,H], 2=Wi_w [H,IN], 3=Wi_b [H],
//         4=Wh_w [H,H], 5=Wh_b [H];  output: hiddens [T,B,H]
// ---------------------------------------------------------------------------
extern "C" void kernel_launch(void* const* d_in, const int* in_sizes, int n_in,
                              void* d_out, int out_size) {
    const float* x   = (const float*)d_in[0];
    const float* h0  = (const float*)d_in[1];
    const float* Wi  = (const float*)d_in[2];
    const float* bi  = (const float*)d_in[3];
    const float* Wh  = (const float*)d_in[4];
    const float* bh  = (const float*)d_in[5];
    float* out = (float*)d_out;

    static bool attr_set = false;
    if (!attr_set) {
        cudaFuncSetAttribute(rnn_persistent,
                             cudaFuncAttributeMaxDynamicSharedMemorySize,
                             SMEM_BYTES);
        attr_set = true;
    }

    // Reset step-barrier counters (each call / replay)
    reset_kernel<<<1, 256>>>();

    // Phase 1: xi for all timesteps, written straight into d_out
    gemm_xi_kernel<<<dim3(H_DIM / 128, M1 / 128), 256>>>(x, Wi, bi, out);

    // Phase 2: persistent recurrence (Wh resident in smem across all steps)
    rnn_persistent<<<dim3(32, 4), 256, SMEM_BYTES>>>(h0, Wh, bh, out);
}